// round 13
// baseline (speedup 1.0000x reference)
#include <cuda_runtime.h>
#include <cuda_bf16.h>
#include <cstdint>

// Problem constants (fixed by the reference: B=16,S=16 -> BS=256)
#define L_TOK   128
#define NARG    8
#define NTOK    8
#define EMB_D   768
#define NP      24            // 3 arg-sets * NARG
#define BDIM    384           // 12 warps
#define NCOL    384           // columns per CTA (half of 768)
#define WSTR    132           // W smem row stride (conflict-free A frags)
#define ESTR    392           // E smem row stride (conflict-free B frags)
#define CHUNK_T 8             // tokens per staged chunk
#define NCHUNKS (L_TOK / CHUNK_T)   // 16
#define STAGES  5             // pipeline depth
#define NT      4             // n-tiles (8 cols) per warp: 12*32 = 384

struct Sm {
    float W[32 * WSTR];                      // 16896 B  (rows 25..31 = 0)
    float ebuf[STAGES * CHUNK_T * ESTR];     // 62720 B  5-stage E chunks
    int   s_ids[L_TOK];
    int   s_arg[NP * NTOK];
    int   s_tot[NP];
    float srow[32];                          // per-row output scale
    float msum;
};

__device__ __forceinline__ uint32_t f2tf32(float x) {
    uint32_t r;
    asm("cvt.rna.tf32.f32 %0, %1;" : "=r"(r) : "f"(x));
    return r;
}

__device__ __forceinline__ void issue_chunk(uint32_t eb_u32,
                                            const float* emb_base,
                                            int c, int tid) {
    const float* src_base = emb_base + (size_t)c * CHUNK_T * EMB_D;
    const int slot = c % STAGES;
    #pragma unroll
    for (int i = 0; i < 2; i++) {            // 768 float4 / 384 threads
        int idx = tid + i * BDIM;
        int row = idx / 96, c4 = idx % 96;
        const float* src = src_base + row * EMB_D + c4 * 4;
        uint32_t dst = eb_u32 +
            (uint32_t)(((slot * CHUNK_T + row) * ESTR + c4 * 4) * 4);
        asm volatile("cp.async.cg.shared.global [%0], [%1], 16;"
                     :: "r"(dst), "l"(src));
    }
}

__global__ void __launch_bounds__(BDIM, 2)
slmuse_gemm_kernel(const int*   __restrict__ sent_ids,
                   const int*   __restrict__ att_mask,
                   const int*   __restrict__ pred_ids,
                   const int*   __restrict__ arg0_ids,
                   const int*   __restrict__ arg1_ids,
                   const float* __restrict__ emb,
                   float*       __restrict__ out,
                   int BS)
{
    extern __shared__ char smraw[];
    Sm* sm = reinterpret_cast<Sm*>(smraw);

    const int tid   = threadIdx.x;
    const int bs    = blockIdx.x >> 1;
    const int chalf = blockIdx.x & 1;
    const int warp  = tid >> 5;        // 0..11
    const int lane  = tid & 31;
    const int g     = lane >> 2;       // groupID 0..7
    const int tig   = lane & 3;        // thread-in-group 0..3
    const int n0w   = warp * (NCOL / 12);   // 32-col slice base (local)

    float* out_mean = out;                               // [BS, D]
    float* out_sets = out + (size_t)BS * EMB_D;          // 3 x [BS, A, D]
    const size_t set_stride = (size_t)BS * NARG * EMB_D;

    const uint32_t eb_u32 = (uint32_t)__cvta_generic_to_shared(sm->ebuf);
    const float* emb_base = emb + (size_t)bs * L_TOK * EMB_D + chalf * NCOL;

    // ---- prologue: issue STAGES-1 = 4 chunks, one commit each ----
    #pragma unroll
    for (int s = 0; s < STAGES - 1; s++) {
        issue_chunk(eb_u32, emb_base, s, tid);
        asm volatile("cp.async.commit_group;");
    }

    // ---- stage ids / arg ids (overlaps the prologue loads) ----
    if (tid < L_TOK) sm->s_ids[tid] = sent_ids[(size_t)bs * L_TOK + tid];
    if (tid < NP * NTOK) {
        int p = tid / NTOK, t = tid % NTOK;
        int set = p / NARG, a = p % NARG;
        const int* src = (set == 0) ? pred_ids : (set == 1) ? arg0_ids : arg1_ids;
        sm->s_arg[tid] = src[((size_t)bs * NARG + a) * NTOK + t];
    }
    if (tid < NP) sm->s_tot[tid] = 0;
    if (tid == BDIM - 1) sm->msum = 0.f;
    __syncthreads();

    // ---- build W (32 x 128): row 0 = mask; rows 1..24 = match weights ----
    for (int task = tid; task < 32 * L_TOK; task += BDIM) {   // ~11 iters
        int m = task >> 7;
        int l = task & (L_TOK - 1);
        float val = 0.f;
        if (m == 0) {
            val = (float)att_mask[(size_t)bs * L_TOK + l];
            atomicAdd(&sm->msum, val);
        } else if (m <= NP) {
            int p = m - 1;
            int sid = sm->s_ids[l];
            int w = 0;
            #pragma unroll
            for (int t = 0; t < NTOK; t++) {
                int aid = sm->s_arg[p * NTOK + t];
                w += (aid != 0 && aid == sid) ? 1 : 0;
            }
            val = (float)w;
            if (w) atomicAdd(&sm->s_tot[p], w);
        }
        sm->W[m * WSTR + l] = val;
    }
    __syncthreads();

    // ---- per-row output scales (visible to epilogue via loop barriers) ----
    if (tid == 0) sm->srow[0] = 1.f / fmaxf(sm->msum, 1.f);
    else if (tid <= NP) {
        int tot = sm->s_tot[tid - 1];
        sm->srow[tid] = (tot > 0) ? (1.f / (float)tot) : 0.f;
    } else if (tid < 32) sm->srow[tid] = 0.f;

    // ---- main loop: 16 chunks, 5-stage pipeline, ONE sync per chunk ----
    float c_[2][NT][4];
    #pragma unroll
    for (int mt = 0; mt < 2; mt++)
        #pragma unroll
        for (int nt = 0; nt < NT; nt++)
            #pragma unroll
            for (int k = 0; k < 4; k++) c_[mt][nt][k] = 0.f;

    for (int c = 0; c < NCHUNKS; c++) {
        // chunk c is commit #(c+1); commits so far = 4 + c -> pending<=3
        asm volatile("cp.async.wait_group 3;");
        __syncthreads();   // publishes chunk c; proves chunk c-1 fully consumed

        if (c + STAGES - 1 < NCHUNKS)
            issue_chunk(eb_u32, emb_base, c + STAGES - 1, tid);
        asm volatile("cp.async.commit_group;");   // always commit (tail: empty)

        const float* EB = sm->ebuf + (c % STAGES) * CHUNK_T * ESTR;
        const int K = c * CHUNK_T;

        // A fragments from W (values exact in tf32: small ints / 0-1)
        uint32_t a[2][4];
        #pragma unroll
        for (int mt = 0; mt < 2; mt++) {
            const float* Wr = sm->W + (mt * 16 + g) * WSTR + K;
            a[mt][0] = __float_as_uint(Wr[tig]);
            a[mt][1] = __float_as_uint(Wr[8 * WSTR + tig]);
            a[mt][2] = __float_as_uint(Wr[tig + 4]);
            a[mt][3] = __float_as_uint(Wr[8 * WSTR + tig + 4]);
        }
        // B fragments from staged E (cvt.rna to tf32)
        uint32_t b[NT][2];
        #pragma unroll
        for (int nt = 0; nt < NT; nt++) {
            const float* Eb = EB + tig * ESTR + n0w + nt * 8 + g;
            b[nt][0] = f2tf32(Eb[0]);
            b[nt][1] = f2tf32(Eb[4 * ESTR]);
        }
        #pragma unroll
        for (int mt = 0; mt < 2; mt++)
            #pragma unroll
            for (int nt = 0; nt < NT; nt++) {
                asm volatile(
                    "mma.sync.aligned.m16n8k8.row.col.f32.tf32.tf32.f32 "
                    "{%0,%1,%2,%3}, {%4,%5,%6,%7}, {%8,%9}, {%0,%1,%2,%3};"
                    : "+f"(c_[mt][nt][0]), "+f"(c_[mt][nt][1]),
                      "+f"(c_[mt][nt][2]), "+f"(c_[mt][nt][3])
                    : "r"(a[mt][0]), "r"(a[mt][1]),
                      "r"(a[mt][2]), "r"(a[mt][3]),
                      "r"(b[nt][0]), "r"(b[nt][1]));
            }
    }

    // ---- epilogue: scale rows, scatter to the three output sections ----
    #pragma unroll
    for (int mt = 0; mt < 2; mt++) {
        const int r0 = mt * 16 + g;      // 0..7 or 16..23  (always valid)
        const int r1 = r0 + 8;           // 8..15 or 24..31 (valid if <=24)
        const float s0 = sm->srow[r0];
        const float s1 = sm->srow[r1 & 31];

        float* base0;
        if (r0 == 0) base0 = out_mean + (size_t)bs * EMB_D;
        else {
            int p = r0 - 1;
            base0 = out_sets + (size_t)(p >> 3) * set_stride
                  + ((size_t)bs * NARG + (p & 7)) * EMB_D;
        }
        float* base1 = nullptr;
        if (r1 <= NP) {
            int p = r1 - 1;              // r1 >= 8, never the mean row
            base1 = out_sets + (size_t)(p >> 3) * set_stride
                  + ((size_t)bs * NARG + (p & 7)) * EMB_D;
        }

        #pragma unroll
        for (int nt = 0; nt < NT; nt++) {
            const int col = chalf * NCOL + n0w + nt * 8 + 2 * tig;
            float2 v0;
            v0.x = c_[mt][nt][0] * s0;
            v0.y = c_[mt][nt][1] * s0;
            *reinterpret_cast<float2*>(base0 + col) = v0;
            if (base1) {
                float2 v1;
                v1.x = c_[mt][nt][2] * s1;
                v1.y = c_[mt][nt][3] * s1;
                *reinterpret_cast<float2*>(base1 + col) = v1;
            }
        }
    }
}

extern "C" void kernel_launch(void* const* d_in, const int* in_sizes, int n_in,
                              void* d_out, int out_size)
{
    const int*   sent = (const int*)  d_in[0];
    const int*   mask = (const int*)  d_in[1];
    const int*   pred = (const int*)  d_in[2];
    const int*   a0   = (const int*)  d_in[3];
    const int*   a1   = (const int*)  d_in[4];
    const float* emb  = (const float*)d_in[5];
    float*       out  = (float*)      d_out;

    const int BS = in_sizes[0] / L_TOK;   // 256

    static int smem_set = 0;
    const int smem_bytes = (int)sizeof(Sm);
    if (!smem_set) {
        cudaFuncSetAttribute(slmuse_gemm_kernel,
                             cudaFuncAttributeMaxDynamicSharedMemorySize,
                             smem_bytes);
        smem_set = 1;
    }

    slmuse_gemm_kernel<<<BS * 2, BDIM, smem_bytes>>>(
        sent, mask, pred, a0, a1, emb, out, BS);
}

// round 14
// speedup vs baseline: 1.0751x; 1.0751x over previous
#include <cuda_runtime.h>
#include <cuda_bf16.h>

// Problem constants (fixed by the reference: B=16,S=16 -> BS=256)
#define L_TOK   128          // tokens per sentence
#define NARG    8            // A
#define NTOK    8            // T
#define EMB_D   768          // D
#define D2      (EMB_D / 2)  // 384 float2 per row
#define NPH     192          // float2 columns owned per CTA (half row)
#define NP      24           // 3 arg-sets * NARG
#define BDIM    384          // 192 mean threads + 192 sparse threads

// flat entry: l (bits 0..6) | w (bits 7..10) | p (bits 11..15)
struct SmemLayout {
    int            s_ids[L_TOK];
    float          s_m[L_TOK];
    int            s_arg[NP * NTOK];
    unsigned char  wtab[NP * L_TOK];        // 3 KB  per (p,l) match weight
    int            cnt[NP];                 // entries per p
    int            cursor[NP];              // placement cursors
    int            offs[NP + 1];            // exclusive scan of cnt
    unsigned short flat[NP * L_TOK + 8];    // 6 KB  events sorted by p (+pad)
    int            s_tot[NP];               // total matched tokens per p
    float          s_inv[NP];               // 1/tot or 0
    int            total_pad;               // padded entry count
};

// Sparse-half-only barrier (warps 6..11, 192 threads)
#define BAR_SPARSE() asm volatile("bar.sync 2, 192;" ::: "memory")

__global__ void __launch_bounds__(BDIM, 3)
slmuse_fused_kernel(const int*   __restrict__ sent_ids,
                    const int*   __restrict__ att_mask,
                    const int*   __restrict__ pred_ids,
                    const int*   __restrict__ arg0_ids,
                    const int*   __restrict__ arg1_ids,
                    const float* __restrict__ emb,
                    float*       __restrict__ out,
                    int BS)
{
    __shared__ SmemLayout sm;

    const int tid   = threadIdx.x;
    const int bs    = blockIdx.x >> 1;        // sentence pair
    const int chalf = blockIdx.x & 1;         // column half (384 cols)

    float* out_mean = out;                               // [BS, D]
    float* out_sets = out + (size_t)BS * EMB_D;          // 3 x [BS, A, D]
    const size_t set_stride = (size_t)BS * NARG * EMB_D;

    // ---- Phase 1: stage ids / mask / arg ids (all threads), ONE sync ----
    if (tid < L_TOK) {
        sm.s_ids[tid] = sent_ids[(size_t)bs * L_TOK + tid];
        sm.s_m[tid]   = (float)att_mask[(size_t)bs * L_TOK + tid];
    }
    if (tid < NP * NTOK) {                 // 192 elements
        int p = tid / NTOK, t = tid % NTOK;
        int set = p / NARG, a = p % NARG;
        const int* src = (set == 0) ? pred_ids : (set == 1) ? arg0_ids : arg1_ids;
        sm.s_arg[tid] = src[((size_t)bs * NARG + a) * NTOK + t];
    }
    if (tid < NP) { sm.cnt[tid] = 0; sm.s_tot[tid] = 0; }
    __syncthreads();   // the ONLY full-block barrier

    if (tid < 192) {
        // ======== MEAN WARPS: stream all 128 tokens immediately ===========
        const int ctid = tid;                 // float2 col within half
        const float2* cb = reinterpret_cast<const float2*>(
                               emb + (size_t)bs * L_TOK * EMB_D)
                           + chalf * NPH + ctid;

        float2 a0 = {0,0}, a1 = {0,0}, a2 = {0,0}, a3 = {0,0};
        float  ms = 0.f;                      // private mask sum (no barrier)
        #pragma unroll 2
        for (int l = 0; l < L_TOK; l += 8) {
            float2 v0 = cb[(l + 0) * D2];
            float2 v1 = cb[(l + 1) * D2];
            float2 v2 = cb[(l + 2) * D2];
            float2 v3 = cb[(l + 3) * D2];
            float2 v4 = cb[(l + 4) * D2];
            float2 v5 = cb[(l + 5) * D2];
            float2 v6 = cb[(l + 6) * D2];
            float2 v7 = cb[(l + 7) * D2];
            float m0 = sm.s_m[l + 0], m1 = sm.s_m[l + 1];
            float m2 = sm.s_m[l + 2], m3 = sm.s_m[l + 3];
            float m4 = sm.s_m[l + 4], m5 = sm.s_m[l + 5];
            float m6 = sm.s_m[l + 6], m7 = sm.s_m[l + 7];
            ms += ((m0 + m1) + (m2 + m3)) + ((m4 + m5) + (m6 + m7));
            a0.x += m0*v0.x; a0.y += m0*v0.y;
            a1.x += m1*v1.x; a1.y += m1*v1.y;
            a2.x += m2*v2.x; a2.y += m2*v2.y;
            a3.x += m3*v3.x; a3.y += m3*v3.y;
            a0.x += m4*v4.x; a0.y += m4*v4.y;
            a1.x += m5*v5.x; a1.y += m5*v5.y;
            a2.x += m6*v6.x; a2.y += m6*v6.y;
            a3.x += m7*v7.x; a3.y += m7*v7.y;
        }
        float minv = 1.f / fmaxf(ms, 1.f);
        float2 r;
        r.x = ((a0.x + a1.x) + (a2.x + a3.x)) * minv;
        r.y = ((a0.y + a1.y) + (a2.y + a3.y)) * minv;
        *reinterpret_cast<float2*>(
            out_mean + (size_t)bs * EMB_D + 2 * (chalf * NPH + ctid)) = r;
    } else {
        // ======== SPARSE WARPS: build list (overlapped), then padded walk ==
        const int stid = tid - 192;            // 0..191
        const int ctid = stid;

        // Build 2a: match weights + per-p counts (16 iterations)
        for (int task = stid; task < NP * L_TOK; task += 192) {
            int p = task >> 7;
            int l = task & (L_TOK - 1);
            int sid = sm.s_ids[l];
            int w = 0;
            #pragma unroll
            for (int t = 0; t < NTOK; t++) {
                int aid = sm.s_arg[p * NTOK + t];
                w += (aid != 0 && aid == sid) ? 1 : 0;
            }
            sm.wtab[task] = (unsigned char)w;
            if (w) {
                atomicAdd(&sm.cnt[p], 1);
                atomicAdd(&sm.s_tot[p], w);
            }
        }
        BAR_SPARSE();

        // Build 2b: exclusive scan (1 thread, 24 elems) + padded total
        if (stid == 0) {
            int run = 0;
            #pragma unroll
            for (int p = 0; p < NP; p++) { sm.offs[p] = run; run += sm.cnt[p]; }
            sm.offs[NP] = run;
            sm.total_pad = (run + 7) & ~7;
        }
        BAR_SPARSE();
        if (stid < NP) {
            sm.cursor[stid] = sm.offs[stid];
            int tot = sm.s_tot[stid];
            sm.s_inv[stid] = (tot > 0) ? (1.f / (float)tot) : 0.f;
        }
        // Pad flat list with sentinels (l=0, w=0, p=NP): walk needs no
        // per-element bounds checks.
        if (stid < 8) sm.flat[sm.offs[NP] + stid] = (unsigned short)(NP << 11);
        BAR_SPARSE();

        // Build 2c: place events into p-sorted flat list
        for (int task = stid; task < NP * L_TOK; task += 192) {
            int w = sm.wtab[task];
            if (w) {
                int p = task >> 7;
                int l = task & (L_TOK - 1);
                int pos = atomicAdd(&sm.cursor[p], 1);
                sm.flat[pos] = (unsigned short)(l | (w << 7) | (p << 11));
            }
        }
        BAR_SPARSE();

        // Walk: p-sorted register walk, float2, no bounds predication.
        const float2* cb = reinterpret_cast<const float2*>(
                               emb + (size_t)bs * L_TOK * EMB_D)
                           + chalf * NPH + ctid;
        const int ocol = 2 * (chalf * NPH + ctid);

        const int total_pad = sm.total_pad;
        float2 acc = {0,0};
        int curp = 0;

        for (int j0 = 0; j0 < total_pad; j0 += 8) {
            float2 vals[8];
            int    es[8];
            #pragma unroll
            for (int k = 0; k < 8; k++) {
                int e = (int)sm.flat[j0 + k];
                es[k] = e;
                // sentinel (p==NP) has w=0: row-0 load is harmless
                vals[k] = cb[(e & 127) * D2];
            }
            #pragma unroll
            for (int k = 0; k < 8; k++) {
                int p = es[k] >> 11;
                if (p != curp) {                       // uniform across half
                    for (int q = curp; q < p && q < NP; q++) {
                        float s = (q == curp) ? sm.s_inv[q] : 0.f;
                        float2 r;
                        r.x = acc.x * s; r.y = acc.y * s;
                        int set = q >> 3, a = q & 7;
                        *reinterpret_cast<float2*>(
                            out_sets + (size_t)set * set_stride
                            + ((size_t)bs * NARG + a) * EMB_D + ocol) = r;
                    }
                    curp = p;
                    acc = make_float2(0.f, 0.f);
                }
                float w = (float)((es[k] >> 7) & 15);
                acc.x += w * vals[k].x; acc.y += w * vals[k].y;
            }
        }
        // tail: remaining p's (including all-empty case); curp may be NP
        for (int q = curp; q < NP; q++) {
            float s = (q == curp) ? sm.s_inv[q] : 0.f;
            float2 r;
            r.x = acc.x * s; r.y = acc.y * s;
            int set = q >> 3, a = q & 7;
            *reinterpret_cast<float2*>(
                out_sets + (size_t)set * set_stride
                + ((size_t)bs * NARG + a) * EMB_D + ocol) = r;
        }
    }
}

extern "C" void kernel_launch(void* const* d_in, const int* in_sizes, int n_in,
                              void* d_out, int out_size)
{
    const int*   sent = (const int*)  d_in[0];
    const int*   mask = (const int*)  d_in[1];
    const int*   pred = (const int*)  d_in[2];
    const int*   a0   = (const int*)  d_in[3];
    const int*   a1   = (const int*)  d_in[4];
    const float* emb  = (const float*)d_in[5];
    float*       out  = (float*)      d_out;

    const int BS = in_sizes[0] / L_TOK;   // 256

    slmuse_fused_kernel<<<BS * 2, BDIM>>>(
        sent, mask, pred, a0, a1, emb, out, BS);
}

// round 15
// speedup vs baseline: 1.5036x; 1.3985x over previous
#include <cuda_runtime.h>
#include <cuda_bf16.h>

// Problem constants (fixed by the reference: B=16,S=16 -> BS=256)
#define L_TOK   128          // tokens per sentence
#define NARG    8            // A
#define NTOK    8            // T
#define EMB_D   768          // D
#define D4      (EMB_D / 4)  // 192 float4 per row
#define NP      24           // 3 arg-sets * NARG
#define PSPLIT  19           // sparse half walks p<19; mean half walks p>=19
#define BDIM    384          // 192 mean threads + 192 sparse threads

// flat entry: l (bits 0..6) | w (bits 7..10) | p (bits 11..15)
struct SmemLayout {
    int            s_ids[L_TOK];
    float          s_m[L_TOK];
    int            s_arg[NP * NTOK];
    unsigned char  wtab[NP * L_TOK];        // 3 KB  per (p,l) match weight
    int            cnt[NP];                 // entries per p
    int            cursor[NP];              // placement cursors
    int            offs[NP + 1];            // exclusive scan of cnt
    unsigned short flat[NP * L_TOK + 8];    // 6 KB  p-sorted events (+pad)
    int            s_tot[NP];               // total matched tokens per p
    float          s_inv[NP];               // 1/tot or 0
};

// Sparse-half-only barrier (warps 6..11, 192 threads)
#define BAR_SPARSE()   asm volatile("bar.sync 2, 192;" ::: "memory")
// Producer(192 sparse arrive) -> consumer(192 mean sync): list-ready handoff
#define LIST_ARRIVE()  asm volatile("bar.arrive 3, 384;" ::: "memory")
#define LIST_WAIT()    asm volatile("bar.sync 3, 384;" ::: "memory")

__device__ __forceinline__ void walk_range(
    const SmemLayout& sm, const float4* cb, int ocol,
    float* out_sets, size_t set_stride, size_t bs,
    int p_beg, int p_end)
{
    const int j_beg = sm.offs[p_beg];
    const int j_end = sm.offs[p_end];

    float4 acc = {0, 0, 0, 0};
    int curp = p_beg;

    for (int j0 = j_beg; j0 < j_end; j0 += 8) {
        float4 vals[8];
        int    es[8];
        #pragma unroll
        for (int k = 0; k < 8; k++) {
            // Reads past j_end are either later-p real entries (emission
            // capped at p_end below) or w=0 sentinels after the list.
            int e = (int)sm.flat[j0 + k];
            es[k]   = e;
            vals[k] = cb[(e & 127) * D4];
        }
        #pragma unroll
        for (int k = 0; k < 8; k++) {
            int p = es[k] >> 11;
            if (p != curp) {                     // uniform across the half
                for (int q = curp; q < p && q < p_end; q++) {
                    float s = (q == curp) ? sm.s_inv[q] : 0.f;
                    float4 r;
                    r.x = acc.x * s; r.y = acc.y * s;
                    r.z = acc.z * s; r.w = acc.w * s;
                    int set = q >> 3, a = q & 7;
                    *reinterpret_cast<float4*>(
                        out_sets + (size_t)set * set_stride
                        + (bs * NARG + a) * EMB_D + ocol) = r;
                }
                curp = p;
                acc = make_float4(0.f, 0.f, 0.f, 0.f);
            }
            float w = (float)((es[k] >> 7) & 15);
            acc.x += w * vals[k].x; acc.y += w * vals[k].y;
            acc.z += w * vals[k].z; acc.w += w * vals[k].w;
        }
    }
    // tail: remaining p's in range (curp may already be >= p_end)
    for (int q = curp; q < p_end; q++) {
        float s = (q == curp) ? sm.s_inv[q] : 0.f;
        float4 r;
        r.x = acc.x * s; r.y = acc.y * s; r.z = acc.z * s; r.w = acc.w * s;
        int set = q >> 3, a = q & 7;
        *reinterpret_cast<float4*>(
            out_sets + (size_t)set * set_stride
            + (bs * NARG + a) * EMB_D + ocol) = r;
    }
}

__global__ void __launch_bounds__(BDIM, 2)
slmuse_fused_kernel(const int*   __restrict__ sent_ids,
                    const int*   __restrict__ att_mask,
                    const int*   __restrict__ pred_ids,
                    const int*   __restrict__ arg0_ids,
                    const int*   __restrict__ arg1_ids,
                    const float* __restrict__ emb,
                    float*       __restrict__ out,
                    int BS)
{
    __shared__ SmemLayout sm;

    const int tid  = threadIdx.x;
    const int bs   = blockIdx.x;              // one CTA per sentence pair

    float* out_mean = out;                               // [BS, D]
    float* out_sets = out + (size_t)BS * EMB_D;          // 3 x [BS, A, D]
    const size_t set_stride = (size_t)BS * NARG * EMB_D;

    // ---- Phase 1: stage ids / mask / arg ids (all threads), ONE sync ----
    if (tid < L_TOK) {
        sm.s_ids[tid] = sent_ids[(size_t)bs * L_TOK + tid];
        sm.s_m[tid]   = (float)att_mask[(size_t)bs * L_TOK + tid];
    }
    if (tid < NP * NTOK) {                 // 192 elements
        int p = tid / NTOK, t = tid % NTOK;
        int set = p / NARG, a = p % NARG;
        const int* src = (set == 0) ? pred_ids : (set == 1) ? arg0_ids : arg1_ids;
        sm.s_arg[tid] = src[((size_t)bs * NARG + a) * NTOK + t];
    }
    if (tid < NP) { sm.cnt[tid] = 0; sm.s_tot[tid] = 0; }
    __syncthreads();   // the ONLY full-block barrier

    const int ctid = (tid < 192) ? tid : tid - 192;
    const float4* cb = reinterpret_cast<const float4*>(
                           emb + (size_t)bs * L_TOK * EMB_D) + ctid;
    const int ocol = 4 * ctid;

    if (tid < 192) {
        // ======== MEAN WARPS: dense stream immediately, then tail p's =====
        float4 a0 = {0,0,0,0}, a1 = {0,0,0,0}, a2 = {0,0,0,0}, a3 = {0,0,0,0};
        float4 a4 = {0,0,0,0}, a5 = {0,0,0,0}, a6 = {0,0,0,0}, a7 = {0,0,0,0};
        float  ms = 0.f;                       // private mask sum
        #pragma unroll 2
        for (int l = 0; l < L_TOK; l += 8) {
            float4 v0 = cb[(l + 0) * D4];
            float4 v1 = cb[(l + 1) * D4];
            float4 v2 = cb[(l + 2) * D4];
            float4 v3 = cb[(l + 3) * D4];
            float4 v4 = cb[(l + 4) * D4];
            float4 v5 = cb[(l + 5) * D4];
            float4 v6 = cb[(l + 6) * D4];
            float4 v7 = cb[(l + 7) * D4];
            float m0 = sm.s_m[l + 0], m1 = sm.s_m[l + 1];
            float m2 = sm.s_m[l + 2], m3 = sm.s_m[l + 3];
            float m4 = sm.s_m[l + 4], m5 = sm.s_m[l + 5];
            float m6 = sm.s_m[l + 6], m7 = sm.s_m[l + 7];
            ms += ((m0 + m1) + (m2 + m3)) + ((m4 + m5) + (m6 + m7));
            a0.x += m0*v0.x; a0.y += m0*v0.y; a0.z += m0*v0.z; a0.w += m0*v0.w;
            a1.x += m1*v1.x; a1.y += m1*v1.y; a1.z += m1*v1.z; a1.w += m1*v1.w;
            a2.x += m2*v2.x; a2.y += m2*v2.y; a2.z += m2*v2.z; a2.w += m2*v2.w;
            a3.x += m3*v3.x; a3.y += m3*v3.y; a3.z += m3*v3.z; a3.w += m3*v3.w;
            a4.x += m4*v4.x; a4.y += m4*v4.y; a4.z += m4*v4.z; a4.w += m4*v4.w;
            a5.x += m5*v5.x; a5.y += m5*v5.y; a5.z += m5*v5.z; a5.w += m5*v5.w;
            a6.x += m6*v6.x; a6.y += m6*v6.y; a6.z += m6*v6.z; a6.w += m6*v6.w;
            a7.x += m7*v7.x; a7.y += m7*v7.y; a7.z += m7*v7.z; a7.w += m7*v7.w;
        }
        float minv = 1.f / fmaxf(ms, 1.f);
        float4 r;
        r.x = (((a0.x+a1.x)+(a2.x+a3.x))+((a4.x+a5.x)+(a6.x+a7.x))) * minv;
        r.y = (((a0.y+a1.y)+(a2.y+a3.y))+((a4.y+a5.y)+(a6.y+a7.y))) * minv;
        r.z = (((a0.z+a1.z)+(a2.z+a3.z))+((a4.z+a5.z)+(a6.z+a7.z))) * minv;
        r.w = (((a0.w+a1.w)+(a2.w+a3.w))+((a4.w+a5.w)+(a6.w+a7.w))) * minv;
        *reinterpret_cast<float4*>(out_mean + (size_t)bs * EMB_D + ocol) = r;

        // Wait for the list (built long ago, in the dense stream's shadow),
        // then take the tail p-range off the sparse half's critical path.
        LIST_WAIT();
        walk_range(sm, cb, ocol, out_sets, set_stride, (size_t)bs,
                   PSPLIT, NP);
    } else {
        // ======== SPARSE WARPS: build list, publish, walk head p-range ====
        const int stid = tid - 192;            // 0..191

        // Build 2a: match weights + per-p counts (16 iterations)
        for (int task = stid; task < NP * L_TOK; task += 192) {
            int p = task >> 7;
            int l = task & (L_TOK - 1);
            int sid = sm.s_ids[l];
            int w = 0;
            #pragma unroll
            for (int t = 0; t < NTOK; t++) {
                int aid = sm.s_arg[p * NTOK + t];
                w += (aid != 0 && aid == sid) ? 1 : 0;
            }
            sm.wtab[task] = (unsigned char)w;
            if (w) {
                atomicAdd(&sm.cnt[p], 1);
                atomicAdd(&sm.s_tot[p], w);
            }
        }
        BAR_SPARSE();

        // Build 2b: exclusive scan (1 thread, 24 elems)
        if (stid == 0) {
            int run = 0;
            #pragma unroll
            for (int p = 0; p < NP; p++) { sm.offs[p] = run; run += sm.cnt[p]; }
            sm.offs[NP] = run;
        }
        BAR_SPARSE();
        if (stid < NP) {
            sm.cursor[stid] = sm.offs[stid];
            int tot = sm.s_tot[stid];
            sm.s_inv[stid] = (tot > 0) ? (1.f / (float)tot) : 0.f;
        }
        // Sentinel pad (l=0, w=0, p=NP): removes bounds checks in walks.
        if (stid < 8) sm.flat[sm.offs[NP] + stid] = (unsigned short)(NP << 11);
        BAR_SPARSE();

        // Build 2c: place events into p-sorted flat list
        for (int task = stid; task < NP * L_TOK; task += 192) {
            int w = sm.wtab[task];
            if (w) {
                int p = task >> 7;
                int l = task & (L_TOK - 1);
                int pos = atomicAdd(&sm.cursor[p], 1);
                sm.flat[pos] = (unsigned short)(l | (w << 7) | (p << 11));
            }
        }
        BAR_SPARSE();

        // Publish the list to the mean half (fence + non-blocking arrive).
        __threadfence_block();
        LIST_ARRIVE();

        // Walk the head p-range.
        walk_range(sm, cb, ocol, out_sets, set_stride, (size_t)bs,
                   0, PSPLIT);
    }
}

extern "C" void kernel_launch(void* const* d_in, const int* in_sizes, int n_in,
                              void* d_out, int out_size)
{
    const int*   sent = (const int*)  d_in[0];
    const int*   mask = (const int*)  d_in[1];
    const int*   pred = (const int*)  d_in[2];
    const int*   a0   = (const int*)  d_in[3];
    const int*   a1   = (const int*)  d_in[4];
    const float* emb  = (const float*)d_in[5];
    float*       out  = (float*)      d_out;

    const int BS = in_sizes[0] / L_TOK;   // 256

    slmuse_fused_kernel<<<BS, BDIM>>>(
        sent, mask, pred, a0, a1, emb, out, BS);
}

// round 17
// speedup vs baseline: 1.6109x; 1.0713x over previous
#include <cuda_runtime.h>
#include <cuda_bf16.h>
#include <cstdint>

// Problem constants (fixed by the reference: B=16,S=16 -> BS=256)
#define L_TOK   128          // tokens per sentence
#define NARG    8            // A
#define NTOK    8            // T
#define EMB_D   768          // D
#define D4      (EMB_D / 4)  // 192 float4 per row
#define NP      24           // 3 arg-sets * NARG
#define PSPLIT  16           // sparse half walks p<16; mean half walks p>=16
#define BDIM    384          // 192 mean threads + 192 sparse threads

#define MST     3            // mean-stream pipeline stages (warp-private)
#define MCT     8            // tokens per staged chunk
#define NMC     (L_TOK / MCT)   // 16 chunks

// flat entry: l (bits 0..6) | w (bits 7..10) | p (bits 11..15)
struct alignas(16) SmemLayout {
    int            s_ids[L_TOK];
    float          s_m[L_TOK];
    int            s_arg[NP * NTOK];
    unsigned char  wtab[NP * L_TOK];        // 3 KB  per (p,l) match weight
    int            cnt[NP];
    int            cursor[NP];
    int            offs[NP + 1];
    unsigned short flat[NP * L_TOK + 8];    // 6 KB  p-sorted events (+pad)
    int            s_tot[NP];
    float          s_inv[NP];
};
// Stage buffer offset: sizeof(SmemLayout) rounded up to 128 B (cp.async
// needs a 16B-aligned shared destination; R16 crashed on exactly this).
#define STAGE_OFF   ((sizeof(SmemLayout) + 127) & ~(size_t)127)
// stage buffer: [6 warps][MST][MCT][32 lanes] float4 = 73728 B
#define STAGE_BYTES (6 * MST * MCT * 32 * 16)

// Sparse-half-only barrier (warps 6..11, 192 threads)
#define BAR_SPARSE()   asm volatile("bar.sync 2, 192;" ::: "memory")
// Producer(192 sparse arrive) -> consumer(192 mean sync): list-ready handoff
#define LIST_ARRIVE()  asm volatile("bar.arrive 3, 384;" ::: "memory")
#define LIST_WAIT()    asm volatile("bar.sync 3, 384;" ::: "memory")

__device__ __forceinline__ void walk_range(
    const SmemLayout* sm, const float4* cb, int ocol,
    float* out_sets, size_t set_stride, size_t bs,
    int p_beg, int p_end)
{
    const int j_beg = sm->offs[p_beg];
    const int j_end = sm->offs[p_end];

    float4 acc = {0, 0, 0, 0};
    int curp = p_beg;

    for (int j0 = j_beg; j0 < j_end; j0 += 8) {
        float4 vals[8];
        int    es[8];
        #pragma unroll
        for (int k = 0; k < 8; k++) {
            // Reads past j_end are later-p entries (emission capped below)
            // or w=0 sentinels after the list.
            int e = (int)sm->flat[j0 + k];
            es[k]   = e;
            vals[k] = cb[(e & 127) * D4];
        }
        #pragma unroll
        for (int k = 0; k < 8; k++) {
            int p = es[k] >> 11;
            if (p != curp) {                     // uniform across the half
                for (int q = curp; q < p && q < p_end; q++) {
                    float s = (q == curp) ? sm->s_inv[q] : 0.f;
                    float4 r;
                    r.x = acc.x * s; r.y = acc.y * s;
                    r.z = acc.z * s; r.w = acc.w * s;
                    int set = q >> 3, a = q & 7;
                    *reinterpret_cast<float4*>(
                        out_sets + (size_t)set * set_stride
                        + (bs * NARG + a) * EMB_D + ocol) = r;
                }
                curp = p;
                acc = make_float4(0.f, 0.f, 0.f, 0.f);
            }
            float w = (float)((es[k] >> 7) & 15);
            acc.x += w * vals[k].x; acc.y += w * vals[k].y;
            acc.z += w * vals[k].z; acc.w += w * vals[k].w;
        }
    }
    for (int q = curp; q < p_end; q++) {
        float s = (q == curp) ? sm->s_inv[q] : 0.f;
        float4 r;
        r.x = acc.x * s; r.y = acc.y * s; r.z = acc.z * s; r.w = acc.w * s;
        int set = q >> 3, a = q & 7;
        *reinterpret_cast<float4*>(
            out_sets + (size_t)set * set_stride
            + (bs * NARG + a) * EMB_D + ocol) = r;
    }
}

__global__ void __launch_bounds__(BDIM, 2)
slmuse_fused_kernel(const int*   __restrict__ sent_ids,
                    const int*   __restrict__ att_mask,
                    const int*   __restrict__ pred_ids,
                    const int*   __restrict__ arg0_ids,
                    const int*   __restrict__ arg1_ids,
                    const float* __restrict__ emb,
                    float*       __restrict__ out,
                    int BS)
{
    extern __shared__ char smraw[];
    SmemLayout* sm = reinterpret_cast<SmemLayout*>(smraw);
    float4* sbuf = reinterpret_cast<float4*>(smraw + STAGE_OFF);

    const int tid  = threadIdx.x;
    const int bs   = blockIdx.x;              // one CTA per sentence pair

    float* out_mean = out;                               // [BS, D]
    float* out_sets = out + (size_t)BS * EMB_D;          // 3 x [BS, A, D]
    const size_t set_stride = (size_t)BS * NARG * EMB_D;

    // ---- Phase 1: stage ids / mask / arg ids (all threads), ONE sync ----
    if (tid < L_TOK) {
        sm->s_ids[tid] = sent_ids[(size_t)bs * L_TOK + tid];
        sm->s_m[tid]   = (float)att_mask[(size_t)bs * L_TOK + tid];
    }
    if (tid < NP * NTOK) {                 // 192 elements
        int p = tid / NTOK, t = tid % NTOK;
        int set = p / NARG, a = p % NARG;
        const int* src = (set == 0) ? pred_ids : (set == 1) ? arg0_ids : arg1_ids;
        sm->s_arg[tid] = src[((size_t)bs * NARG + a) * NTOK + t];
    }
    if (tid < NP) { sm->cnt[tid] = 0; sm->s_tot[tid] = 0; }
    __syncthreads();   // the ONLY full-block barrier

    const int ctid = (tid < 192) ? tid : tid - 192;   // float4 column
    const float4* cb = reinterpret_cast<const float4*>(
                           emb + (size_t)bs * L_TOK * EMB_D) + ctid;
    const int ocol = 4 * ctid;

    if (tid < 192) {
        // ======== MEAN WARPS: cp.async warp-private staged stream =========
        const int wm = tid >> 5;              // mean warp 0..5
        // this thread's slot base (lane-resolved)
        uint32_t sb_u32 = (uint32_t)__cvta_generic_to_shared(
                              sbuf + (wm * MST * MCT * 32) + (tid & 31));

        // prologue: issue chunks 0..MST-1
        #pragma unroll
        for (int s = 0; s < MST; s++) {
            const float4* src = cb + (size_t)(s * MCT) * D4;
            #pragma unroll
            for (int t = 0; t < MCT; t++) {
                uint32_t dst = sb_u32 + (uint32_t)(((s * MCT + t) * 32) * 16);
                asm volatile("cp.async.cg.shared.global [%0], [%1], 16;"
                             :: "r"(dst), "l"(src + (size_t)t * D4));
            }
            asm volatile("cp.async.commit_group;");
        }

        float4 a0 = {0,0,0,0}, a1 = {0,0,0,0}, a2 = {0,0,0,0}, a3 = {0,0,0,0};
        float  ms = 0.f;

        for (int c = 0; c < NMC; c++) {
            asm volatile("cp.async.wait_group %0;" :: "n"(MST - 1));
            // chunk c resident in slot c%MST (warp-private: no bar needed)
            const int slot = c % MST;
            const int base = wm * MST * MCT * 32 + slot * MCT * 32 + (tid & 31);

            float4 v[MCT];
            #pragma unroll
            for (int t = 0; t < MCT; t++)
                v[t] = sbuf[base + t * 32];

            const int l0 = c * MCT;
            #pragma unroll
            for (int t = 0; t < MCT; t += 4) {
                float m0 = sm->s_m[l0 + t + 0], m1 = sm->s_m[l0 + t + 1];
                float m2 = sm->s_m[l0 + t + 2], m3 = sm->s_m[l0 + t + 3];
                ms += (m0 + m1) + (m2 + m3);
                a0.x += m0*v[t+0].x; a0.y += m0*v[t+0].y;
                a0.z += m0*v[t+0].z; a0.w += m0*v[t+0].w;
                a1.x += m1*v[t+1].x; a1.y += m1*v[t+1].y;
                a1.z += m1*v[t+1].z; a1.w += m1*v[t+1].w;
                a2.x += m2*v[t+2].x; a2.y += m2*v[t+2].y;
                a2.z += m2*v[t+2].z; a2.w += m2*v[t+2].w;
                a3.x += m3*v[t+3].x; a3.y += m3*v[t+3].y;
                a3.z += m3*v[t+3].z; a3.w += m3*v[t+3].w;
            }

            // refill this slot with chunk c+MST
            if (c + MST < NMC) {
                const float4* src = cb + (size_t)((c + MST) * MCT) * D4;
                #pragma unroll
                for (int t = 0; t < MCT; t++) {
                    uint32_t dst = sb_u32 + (uint32_t)(((slot * MCT + t) * 32) * 16);
                    asm volatile("cp.async.cg.shared.global [%0], [%1], 16;"
                                 :: "r"(dst), "l"(src + (size_t)t * D4));
                }
            }
            asm volatile("cp.async.commit_group;");   // empty in tail: keeps count
        }

        float minv = 1.f / fmaxf(ms, 1.f);
        float4 r;
        r.x = ((a0.x + a1.x) + (a2.x + a3.x)) * minv;
        r.y = ((a0.y + a1.y) + (a2.y + a3.y)) * minv;
        r.z = ((a0.z + a1.z) + (a2.z + a3.z)) * minv;
        r.w = ((a0.w + a1.w) + (a2.w + a3.w)) * minv;
        *reinterpret_cast<float4*>(out_mean + (size_t)bs * EMB_D + ocol) = r;

        // Take the tail p-range off the sparse half's critical path.
        LIST_WAIT();
        walk_range(sm, cb, ocol, out_sets, set_stride, (size_t)bs,
                   PSPLIT, NP);
    } else {
        // ======== SPARSE WARPS: build list, publish, walk head p-range ====
        const int stid = tid - 192;            // 0..191

        // Build 2a: match weights + per-p counts (16 iterations)
        for (int task = stid; task < NP * L_TOK; task += 192) {
            int p = task >> 7;
            int l = task & (L_TOK - 1);
            int sid = sm->s_ids[l];
            int w = 0;
            #pragma unroll
            for (int t = 0; t < NTOK; t++) {
                int aid = sm->s_arg[p * NTOK + t];
                w += (aid != 0 && aid == sid) ? 1 : 0;
            }
            sm->wtab[task] = (unsigned char)w;
            if (w) {
                atomicAdd(&sm->cnt[p], 1);
                atomicAdd(&sm->s_tot[p], w);
            }
        }
        BAR_SPARSE();

        // Build 2b: exclusive scan (1 thread, 24 elems)
        if (stid == 0) {
            int run = 0;
            #pragma unroll
            for (int p = 0; p < NP; p++) { sm->offs[p] = run; run += sm->cnt[p]; }
            sm->offs[NP] = run;
        }
        BAR_SPARSE();
        if (stid < NP) {
            sm->cursor[stid] = sm->offs[stid];
            int tot = sm->s_tot[stid];
            sm->s_inv[stid] = (tot > 0) ? (1.f / (float)tot) : 0.f;
        }
        // Sentinel pad (l=0, w=0, p=NP): removes bounds checks in walks.
        if (stid < 8) sm->flat[sm->offs[NP] + stid] = (unsigned short)(NP << 11);
        BAR_SPARSE();

        // Build 2c: place events into p-sorted flat list
        for (int task = stid; task < NP * L_TOK; task += 192) {
            int w = sm->wtab[task];
            if (w) {
                int p = task >> 7;
                int l = task & (L_TOK - 1);
                int pos = atomicAdd(&sm->cursor[p], 1);
                sm->flat[pos] = (unsigned short)(l | (w << 7) | (p << 11));
            }
        }
        BAR_SPARSE();

        // Publish the list to the mean half (fence + non-blocking arrive).
        __threadfence_block();
        LIST_ARRIVE();

        // Walk the head p-range (direct LDG; hits L2 filled by cp.async.cg).
        walk_range(sm, cb, ocol, out_sets, set_stride, (size_t)bs,
                   0, PSPLIT);
    }
}

extern "C" void kernel_launch(void* const* d_in, const int* in_sizes, int n_in,
                              void* d_out, int out_size)
{
    const int*   sent = (const int*)  d_in[0];
    const int*   mask = (const int*)  d_in[1];
    const int*   pred = (const int*)  d_in[2];
    const int*   a0   = (const int*)  d_in[3];
    const int*   a1   = (const int*)  d_in[4];
    const float* emb  = (const float*)d_in[5];
    float*       out  = (float*)      d_out;

    const int BS = in_sizes[0] / L_TOK;   // 256
    const int smem_bytes = (int)(STAGE_OFF + STAGE_BYTES);

    static int smem_set = 0;
    if (!smem_set) {
        cudaFuncSetAttribute(slmuse_fused_kernel,
                             cudaFuncAttributeMaxDynamicSharedMemorySize,
                             smem_bytes);
        smem_set = 1;
    }

    slmuse_fused_kernel<<<BS, BDIM, smem_bytes>>>(
        sent, mask, pred, a0, a1, emb, out, BS);
}